// round 6
// baseline (speedup 1.0000x reference)
#include <cuda_runtime.h>
#include <cuda_bf16.h>
#include <cstdint>
#include <math.h>

// Problem constants
#define Bb 4
#define Hh 4
#define Ss 2048
#define Dd 512
#define Uu 1024
#define BS 8192          // Bb*Ss
#define HU 4096          // Hh*Uu

// Arch feature gate: tcgen05 only exists on the 'a' variants.
#if defined(__CUDA_ARCH_FEAT_SM103_ALL) || defined(__CUDA_ARCH_FEAT_SM100_ALL)
#define HAS_TCGEN05 1
#else
#define HAS_TCGEN05 0
#endif

// ---------------------------------------------------------------------------
// Device scratch (no cudaMalloc allowed) — round-3 proven fp32 layout
// ---------------------------------------------------------------------------
__device__ float g_xn[BS * Dd];                       // 16 MB
__device__ float g_q[(size_t)Hh * BS * Uu];           // 134 MB
__device__ float g_k[(size_t)Hh * BS * Uu];           // 134 MB
__device__ float g_v[(size_t)Hh * BS * Uu];           // 134 MB
__device__ float g_vt[(size_t)Hh * BS * Uu];          // 134 MB (V^T [h][b][u][t])
__device__ float g_sc[(size_t)Bb * Hh * Ss * Ss];     // 268 MB
__device__ float g_cat[(size_t)BS * HU];              // 134 MB
__device__ float g_wt[(size_t)3 * Hh * Uu * Dd];      // 25 MB  (W^T for q,k,v)
__device__ float g_wot[(size_t)Dd * HU];              // 8 MB   (Wout^T [512][4096])

// ---------------------------------------------------------------------------
// PTX helpers (guarded where sm_103a-only)
// ---------------------------------------------------------------------------
__device__ __forceinline__ uint32_t smem_u32(const void* p) {
    uint32_t a;
    asm("{ .reg .u64 t; cvta.to.shared.u64 t, %1; cvt.u32.u64 %0, t; }" : "=r"(a) : "l"(p));
    return a;
}

#if HAS_TCGEN05
__device__ __forceinline__ uint32_t elect_one() {
    uint32_t pred;
    asm volatile("{\n\t.reg .pred p;\n\telect.sync _|p, 0xFFFFFFFF;\n\t"
                 "selp.b32 %0, 1, 0, p;\n\t}" : "=r"(pred));
    return pred;
}
#define MBAR_INIT(addr, cnt) \
    asm volatile("mbarrier.init.shared.b64 [%0], %1;" :: "r"(addr), "r"(cnt) : "memory")
#define MBAR_WAIT(addr, parity) do {                                              \
    uint32_t _m = (addr), _p = (parity), _d;                                      \
    asm volatile("{\n\t.reg .pred p;\n\t"                                         \
        "mbarrier.try_wait.parity.acquire.cta.shared::cta.b64 p, [%1], %2;\n\t"   \
        "selp.b32 %0, 1, 0, p;\n\t}" : "=r"(_d) : "r"(_m), "r"(_p) : "memory");   \
    if (!_d) {                                                                    \
        asm volatile("{\n\t.reg .pred P1;\n\t"                                    \
            "W_%=:\n\t"                                                           \
            "mbarrier.try_wait.parity.acquire.cta.shared::cta.b64 P1, [%0], %1, 0x989680;\n\t" \
            "@P1 bra.uni D_%=;\n\t"                                               \
            "bra.uni W_%=;\n\t"                                                   \
            "D_%=:\n\t}" :: "r"(_m), "r"(_p) : "memory");                         \
    }                                                                             \
} while (0)
#define TC_ALLOC(smem_addr, n) \
    asm volatile("tcgen05.alloc.cta_group::1.sync.aligned.shared::cta.b32 [%0], %1;" \
                 :: "r"(smem_addr), "r"((uint32_t)(n)) : "memory")
#define TC_DEALLOC(tmem, n) \
    asm volatile("tcgen05.dealloc.cta_group::1.sync.aligned.b32 %0, %1;" :: "r"(tmem), "r"((uint32_t)(n)))
#define TC_COMMIT(mbar) \
    asm volatile("tcgen05.commit.cta_group::1.mbarrier::arrive::one.shared::cluster.b64 [%0];" \
                 :: "r"(mbar) : "memory")
#define TC_FENCE_AFTER()  asm volatile("tcgen05.fence::after_thread_sync;" ::: "memory")
#define TC_WAIT_LD()      asm volatile("tcgen05.wait::ld.sync.aligned;" ::: "memory")
#define FENCE_ASYNC()     asm volatile("fence.proxy.async.shared::cta;" ::: "memory")

#define LDTM_X32(r, addr)                                                         \
    asm volatile("tcgen05.ld.sync.aligned.32x32b.x32.b32 "                        \
        "{%0, %1, %2, %3, %4, %5, %6, %7, %8, %9, %10, %11, %12, %13, %14, %15, " \
        " %16, %17, %18, %19, %20, %21, %22, %23, %24, %25, %26, %27, %28, %29, %30, %31}, [%32];" \
        : "=r"((r)[0]), "=r"((r)[1]), "=r"((r)[2]), "=r"((r)[3]),                 \
          "=r"((r)[4]), "=r"((r)[5]), "=r"((r)[6]), "=r"((r)[7]),                 \
          "=r"((r)[8]), "=r"((r)[9]), "=r"((r)[10]), "=r"((r)[11]),               \
          "=r"((r)[12]), "=r"((r)[13]), "=r"((r)[14]), "=r"((r)[15]),             \
          "=r"((r)[16]), "=r"((r)[17]), "=r"((r)[18]), "=r"((r)[19]),             \
          "=r"((r)[20]), "=r"((r)[21]), "=r"((r)[22]), "=r"((r)[23]),             \
          "=r"((r)[24]), "=r"((r)[25]), "=r"((r)[26]), "=r"((r)[27]),             \
          "=r"((r)[28]), "=r"((r)[29]), "=r"((r)[30]), "=r"((r)[31])              \
        : "r"(addr))

__device__ __forceinline__ void sts128(uint32_t addr, uint32_t a, uint32_t b,
                                       uint32_t c, uint32_t d) {
    asm volatile("st.shared.v4.b32 [%0], {%1,%2,%3,%4};"
                 :: "r"(addr), "r"(a), "r"(b), "r"(c), "r"(d) : "memory");
}

// pack two f32 into bf16x2 (low = x) with a single cvt
__device__ __forceinline__ uint32_t packbf2(float x, float y) {
    uint32_t r;
    asm("cvt.rn.bf16x2.f32 %0, %1, %2;" : "=r"(r) : "f"(y), "f"(x));
    return r;
}

// SMEM descriptor, SW128, LBO=1 (16B), SBO=64 (1024B)
__device__ __forceinline__ uint64_t make_desc(uint32_t addr) {
    const uint64_t base = (2ULL << 61) | (1ULL << 46) | (64ULL << 32) | (1ULL << 16);
    return base | (uint64_t)((addr >> 4) & 0x3FFF);
}
__device__ __forceinline__ void mma_ss(uint32_t d, uint64_t ad, uint64_t bd,
                                       uint32_t idesc, uint32_t en) {
    asm volatile("{\n\t.reg .pred p;\n\tsetp.ne.u32 p, %4, 0;\n\t"
        "tcgen05.mma.cta_group::1.kind::f16 [%0], %1, %2, %3, {%5, %5, %5, %5}, p;\n\t}"
        :: "r"(d), "l"(ad), "l"(bd), "r"(idesc), "r"(en), "r"(0u) : "memory");
}
#endif  // HAS_TCGEN05

// idesc: fp32 accum, bf16 A/B, M=128, N=128 (round-3 proven)
#define IDESC 0x8200490u

// SMEM layout (round-3 proven): 2 stages x (A hi/lo 256x64, B hi/lo 128x64)
#define SM_AHI(s) ((s) * 98304 + 0)
#define SM_ALO(s) ((s) * 98304 + 32768)
#define SM_BHI(s) ((s) * 98304 + 65536)
#define SM_BLO(s) ((s) * 98304 + 81920)
#define SM_MBAR(s) (196608 + (s) * 8)
#define SM_TPTR 196624
#define SMEM_BYTES 196640

#if HAS_TCGEN05
// ---------------------------------------------------------------------------
// Optimized stage: fp32 K-major tile (rows x 64) -> hi/lo bf16 SW128 planes.
// Per thread-iter: 8 consecutive fp32, 2x LDG.128 -> 2x STS.128.
// Smem contents byte-identical to round-3's stage (same rn split numerics).
// rows staged = ITERS * 32.
// ---------------------------------------------------------------------------
template <int ITERS>
__device__ __forceinline__ void stage(const float* __restrict__ src, int ld,
                                      uint32_t hi, uint32_t lo, int tid) {
#pragma unroll
    for (int i = 0; i < ITERS; i++) {
        int idx = tid + i * 256;
        int r = idx >> 3, q = idx & 7;   // 8 threads per row, 8 elems each
        const float* p = src + (size_t)r * ld + (q << 3);
        float4 a = *(const float4*)p;
        float4 b = *(const float4*)(p + 4);

        uint32_t h0 = packbf2(a.x, a.y);
        uint32_t h1 = packbf2(a.z, a.w);
        uint32_t h2 = packbf2(b.x, b.y);
        uint32_t h3 = packbf2(b.z, b.w);

        uint32_t l0 = packbf2(a.x - __uint_as_float(h0 << 16),
                              a.y - __uint_as_float(h0 & 0xFFFF0000u));
        uint32_t l1 = packbf2(a.z - __uint_as_float(h1 << 16),
                              a.w - __uint_as_float(h1 & 0xFFFF0000u));
        uint32_t l2 = packbf2(b.x - __uint_as_float(h2 << 16),
                              b.y - __uint_as_float(h2 & 0xFFFF0000u));
        uint32_t l3 = packbf2(b.z - __uint_as_float(h3 << 16),
                              b.w - __uint_as_float(h3 & 0xFFFF0000u));

        uint32_t o = (uint32_t)(r * 128 + (q << 4));
        o ^= (o >> 3) & 0x70;
        sts128(hi + o, h0, h1, h2, h3);
        sts128(lo + o, l0, l1, l2, l3);
    }
}
#endif

// ---------------------------------------------------------------------------
// Main GEMM (round-3 proven): C[256 x 128] = A[256 x kmax] * B[128 x kmax]^T
// fp32 K-major operands, bf16-split 3-pass emulation. kmax multiple of 64.
// ---------------------------------------------------------------------------
__device__ void gemm_main(const float* __restrict__ A, int lda,
                          const float* __restrict__ B, int ldb,
                          float* __restrict__ C, int ldc, int kmax) {
#if HAS_TCGEN05
    extern __shared__ char smem[];
    uint32_t sb = smem_u32(smem);
    int tid = threadIdx.x;
    int wid = tid >> 5;
    int lane = tid & 31;

    if (wid == 0) TC_ALLOC(sb + SM_TPTR, 256);
    if (tid == 0) { MBAR_INIT(sb + SM_MBAR(0), 1); MBAR_INIT(sb + SM_MBAR(1), 1); }
    __syncthreads();
    uint32_t tmem = *(volatile uint32_t*)(smem + SM_TPTR);

    int nch = kmax >> 6;
    int ph0 = 0, ph1 = 0;

    for (int c = 0; c < nch; c++) {
        int s = c & 1;
        if (c >= 2) {
            if (s == 0) { MBAR_WAIT(sb + SM_MBAR(0), ph0 & 1); ph0++; }
            else        { MBAR_WAIT(sb + SM_MBAR(1), ph1 & 1); ph1++; }
        }
        stage<8>(A + c * 64, lda, sb + SM_AHI(s), sb + SM_ALO(s), tid);
        stage<4>(B + c * 64, ldb, sb + SM_BHI(s), sb + SM_BLO(s), tid);
        FENCE_ASYNC();
        __syncthreads();
        if (wid == 0) {
            if (elect_one()) {
                uint64_t ahi = make_desc(sb + SM_AHI(s));
                uint64_t alo = make_desc(sb + SM_ALO(s));
                uint64_t bhi = make_desc(sb + SM_BHI(s));
                uint64_t blo = make_desc(sb + SM_BLO(s));
                uint64_t ap[3] = {ahi, ahi, alo};
                uint64_t bp[3] = {bhi, blo, bhi};
#pragma unroll
                for (int half = 0; half < 2; half++) {
                    uint32_t d = tmem + (half << 7);
                    uint64_t ao = (uint64_t)(half * 1024);  // +128 rows * 128B / 16
#pragma unroll
                    for (int pp = 0; pp < 3; pp++) {
#pragma unroll
                        for (int ks = 0; ks < 4; ks++) {
                            uint32_t en = !(c == 0 && pp == 0 && ks == 0);
                            mma_ss(d, ap[pp] + ao + ks * 2, bp[pp] + ks * 2, IDESC, en);
                        }
                    }
                }
                TC_COMMIT(sb + SM_MBAR(s));
            }
        }
    }

    // Drain outstanding MMAs
    if (nch > 0) MBAR_WAIT(sb + SM_MBAR(0), ph0 & 1);
    if (nch > 1) MBAR_WAIT(sb + SM_MBAR(1), ph1 & 1);
    TC_FENCE_AFTER();
    __syncthreads();

    // Epilogue: TMEM -> smem bounce -> coalesced gmem (round-3 proven)
    int halfw = wid >> 2;
    int grow = (halfw << 7) + ((wid & 3) << 5) + lane;  // 0..255
    float* sbuf = (float*)smem;                          // reuse stage area
#pragma unroll
    for (int bt = 0; bt < 4; bt++) {
        uint32_t r[32];
        LDTM_X32(r, tmem + (halfw << 7) + bt * 32);
        TC_WAIT_LD();
#pragma unroll
        for (int j = 0; j < 32; j++) sbuf[grow * 33 + j] = __uint_as_float(r[j]);
        __syncthreads();
#pragma unroll
        for (int i = 0; i < 8; i++) {
            int idx = tid + i * 256;
            int row = idx >> 3, c4 = (idx & 7) << 2;
            float4 v = make_float4(sbuf[row * 33 + c4], sbuf[row * 33 + c4 + 1],
                                   sbuf[row * 33 + c4 + 2], sbuf[row * 33 + c4 + 3]);
            *(float4*)(C + (size_t)row * ldc + bt * 32 + c4) = v;
        }
        __syncthreads();
    }
    if (wid == 0) TC_DEALLOC(tmem, 256);

#else  // ----- fp32 SIMT fallback (plain sm_103 PTX pass) -----
    extern __shared__ char smem[];
    float (*As)[128] = (float (*)[128])smem;                    // [16][128]
    float (*Bs)[128] = (float (*)[128])(smem + 16 * 128 * 4);   // [16][128]
    const int tid = threadIdx.x;
    const int tx = tid & 15, ty = tid >> 4;

    for (int half = 0; half < 2; half++) {
        const float* Ah = A + (size_t)(half * 128) * lda;
        float acc[8][8];
#pragma unroll
        for (int i = 0; i < 8; i++)
#pragma unroll
            for (int j = 0; j < 8; j++) acc[i][j] = 0.0f;

        for (int k0 = 0; k0 < kmax; k0 += 16) {
#pragma unroll
            for (int i = 0; i < 2; i++) {
                int idx = tid + i * 256;
                int r = idx >> 2, c = (idx & 3) << 2;
                float4 v = *(const float4*)(Ah + (size_t)r * lda + k0 + c);
                As[c + 0][r] = v.x; As[c + 1][r] = v.y;
                As[c + 2][r] = v.z; As[c + 3][r] = v.w;
                float4 w = *(const float4*)(B + (size_t)r * ldb + k0 + c);
                Bs[c + 0][r] = w.x; Bs[c + 1][r] = w.y;
                Bs[c + 2][r] = w.z; Bs[c + 3][r] = w.w;
            }
            __syncthreads();
#pragma unroll
            for (int k = 0; k < 16; k++) {
                float a[8], b[8];
#pragma unroll
                for (int j = 0; j < 8; j++) { a[j] = As[k][ty * 8 + j]; b[j] = Bs[k][tx * 8 + j]; }
#pragma unroll
                for (int i = 0; i < 8; i++)
#pragma unroll
                    for (int j = 0; j < 8; j++)
                        acc[i][j] = fmaf(a[i], b[j], acc[i][j]);
            }
            __syncthreads();
        }
#pragma unroll
        for (int i = 0; i < 8; i++) {
            float* cr = C + (size_t)(half * 128 + ty * 8 + i) * ldc + tx * 8;
#pragma unroll
            for (int j = 0; j < 8; j++) cr[j] = acc[i][j];
        }
        __syncthreads();
    }
#endif
}

// ---------------------------------------------------------------------------
// Block reduction (256 threads)
// ---------------------------------------------------------------------------
__device__ __forceinline__ float block_reduce(float v, bool is_max) {
    __shared__ float red[8];
    int lane = threadIdx.x & 31, w = threadIdx.x >> 5;
#pragma unroll
    for (int o = 16; o; o >>= 1) {
        float u = __shfl_xor_sync(0xffffffffu, v, o);
        v = is_max ? fmaxf(v, u) : (v + u);
    }
    if (lane == 0) red[w] = v;
    __syncthreads();
    if (w == 0) {
        float t = (lane < 8) ? red[lane] : (is_max ? -3.4e38f : 0.0f);
#pragma unroll
        for (int o = 4; o; o >>= 1) {
            float u = __shfl_xor_sync(0xffffffffu, t, o);
            t = is_max ? fmaxf(t, u) : (t + u);
        }
        if (lane == 0) red[0] = t;
    }
    __syncthreads();
    float r = red[0];
    __syncthreads();
    return r;
}

// ---------------------------------------------------------------------------
// LayerNorm
// ---------------------------------------------------------------------------
__global__ void ln_kernel(const float* __restrict__ x,
                          const float* __restrict__ gamma,
                          const float* __restrict__ beta) {
    int row = blockIdx.x;
    const float* xr = x + (size_t)row * Dd;
    float* o = g_xn + (size_t)row * Dd;
    int t = threadIdx.x;
    float v0 = xr[t], v1 = xr[t + 256];
    float mu = block_reduce(v0 + v1, false) * (1.0f / Dd);
    float d0 = v0 - mu, d1 = v1 - mu;
    float var = block_reduce(d0 * d0 + d1 * d1, false) * (1.0f / Dd);
    float inv = 1.0f / sqrtf(var + 1e-6f);
    o[t]       = d0 * inv * gamma[t]       + beta[t];
    o[t + 256] = d1 * inv * gamma[t + 256] + beta[t + 256];
}

// ---------------------------------------------------------------------------
// Tiled fp32 transpose: [R][C] -> [C][R], batched over blockIdx.z
// ---------------------------------------------------------------------------
__device__ __forceinline__ void tr_dev(const float* __restrict__ src,
                                       float* __restrict__ dst, int R, int C) {
    __shared__ float t[32][33];
    size_t bo = (size_t)blockIdx.z * R * C;
    int c0 = blockIdx.x * 32, r0 = blockIdx.y * 32;
    int tx = threadIdx.x, ty = threadIdx.y;
#pragma unroll
    for (int i = 0; i < 4; i++)
        t[ty + i * 8][tx] = src[bo + (size_t)(r0 + ty + i * 8) * C + c0 + tx];
    __syncthreads();
#pragma unroll
    for (int i = 0; i < 4; i++)
        dst[bo + (size_t)(c0 + ty + i * 8) * R + r0 + tx] = t[tx][ty + i * 8];
}

__global__ void trw_kernel(const float* __restrict__ src, int wsel) {
    tr_dev(src, g_wt + (size_t)wsel * Hh * Uu * Dd, Dd, Uu);
}
__global__ void trwo_kernel(const float* __restrict__ src) {
    tr_dev(src, g_wot, HU, Dd);
}
__global__ void trv_kernel() {
    tr_dev(g_v, g_vt, Ss, Uu);
}

// ---------------------------------------------------------------------------
// GEMM wrappers
// ---------------------------------------------------------------------------
__global__ __launch_bounds__(256, 1) void qkv_tc() {
    int z = blockIdx.z;
    int which = z >> 2, h = z & 3;
    const float* Bp = g_wt + (size_t)z * Uu * Dd;
    float* Cb = (which == 0 ? g_q : which == 1 ? g_k : g_v) + (size_t)h * BS * Uu;
    int br = blockIdx.y * 256, bc = blockIdx.x * 128;
    gemm_main(g_xn + (size_t)br * Dd, Dd, Bp + (size_t)bc * Dd, Dd,
              Cb + (size_t)br * Uu + bc, Uu, Dd);
}

__global__ __launch_bounds__(256, 1) void scores_tc() {
    int br = blockIdx.y * 256, bc = blockIdx.x * 128;
    if (bc >= br + 256) return;  // fully above causal diagonal
    int z = blockIdx.z, b = z >> 2, h = z & 3;
    const float* Qh = g_q + ((size_t)h * BS + (size_t)b * Ss) * Uu;
    const float* Kh = g_k + ((size_t)h * BS + (size_t)b * Ss) * Uu;
    float* C = g_sc + (size_t)(b * Hh + h) * Ss * Ss;
    gemm_main(Qh + (size_t)br * Uu, Uu, Kh + (size_t)bc * Uu, Uu,
              C + (size_t)br * Ss + bc, Ss, Uu);
}

__global__ __launch_bounds__(256, 1) void pv_tc() {
    int z = blockIdx.z, b = z >> 2, h = z & 3;
    int br = blockIdx.y * 256, bc = blockIdx.x * 128;
    const float* P = g_sc + (size_t)(b * Hh + h) * Ss * Ss;
    const float* Vt = g_vt + (size_t)(h * Bb + b) * Uu * Ss;
    float* C = g_cat + (size_t)(b * Ss + br) * HU + h * Uu + bc;
    gemm_main(P + (size_t)br * Ss, Ss, Vt + (size_t)bc * Ss, Ss, C, HU, br + 256);
}

__global__ __launch_bounds__(256, 1) void out_tc(float* __restrict__ out) {
    int br = blockIdx.y * 256, bc = blockIdx.x * 128;
    gemm_main(g_cat + (size_t)br * HU, HU, g_wot + (size_t)bc * HU, HU,
              out + (size_t)br * Dd + bc, Dd, HU);
}

// ---------------------------------------------------------------------------
// Softmax (causal, unscaled). Zero-fills (i, 256-block end) for PV.
// ---------------------------------------------------------------------------
__global__ void softmax_kernel() {
    int row = blockIdx.x;
    int i = row & (Ss - 1);
    float* r = g_sc + (size_t)row * Ss;
    int n = i + 1;
    int t = threadIdx.x;

    float v[8];
    float m = -3.4e38f;
#pragma unroll
    for (int c = 0; c < 8; c++) {
        int j = t + c * 256;
        v[c] = (j < n) ? r[j] : -3.4e38f;
        m = fmaxf(m, v[c]);
    }
    m = block_reduce(m, true);
    float s = 0.0f;
#pragma unroll
    for (int c = 0; c < 8; c++) {
        v[c] = expf(v[c] - m);
        s += v[c];
    }
    s = block_reduce(s, false);
    float inv = 1.0f / s;
#pragma unroll
    for (int c = 0; c < 8; c++) {
        int j = t + c * 256;
        if (j < n) r[j] = v[c] * inv;
    }
    int end = ((i >> 8) + 1) << 8;   // 256-aligned (PV tile k-extent)
    for (int j = n + t; j < end; j += 256) r[j] = 0.0f;
}

// ---------------------------------------------------------------------------
extern "C" void kernel_launch(void* const* d_in, const int* in_sizes, int n_in,
                              void* d_out, int out_size) {
    const float* x     = (const float*)d_in[0];
    const float* gamma = (const float*)d_in[1];
    const float* beta  = (const float*)d_in[2];
    const float* Wq    = (const float*)d_in[3];
    const float* Wk    = (const float*)d_in[4];
    const float* Wv    = (const float*)d_in[5];
    const float* Wout  = (const float*)d_in[6];
    float* out = (float*)d_out;

    cudaFuncSetAttribute(qkv_tc,    cudaFuncAttributeMaxDynamicSharedMemorySize, SMEM_BYTES);
    cudaFuncSetAttribute(scores_tc, cudaFuncAttributeMaxDynamicSharedMemorySize, SMEM_BYTES);
    cudaFuncSetAttribute(pv_tc,     cudaFuncAttributeMaxDynamicSharedMemorySize, SMEM_BYTES);
    cudaFuncSetAttribute(out_tc,    cudaFuncAttributeMaxDynamicSharedMemorySize, SMEM_BYTES);

    dim3 tb(32, 8);

    ln_kernel<<<BS, 256>>>(x, gamma, beta);
    trw_kernel<<<dim3(Uu / 32, Dd / 32, Hh), tb>>>(Wq, 0);
    trw_kernel<<<dim3(Uu / 32, Dd / 32, Hh), tb>>>(Wk, 1);
    trw_kernel<<<dim3(Uu / 32, Dd / 32, Hh), tb>>>(Wv, 2);
    trwo_kernel<<<dim3(Dd / 32, HU / 32, 1), tb>>>(Wout);

    qkv_tc<<<dim3(Uu / 128, BS / 256, 12), 256, SMEM_BYTES>>>();
    trv_kernel<<<dim3(Uu / 32, Ss / 32, Bb * Hh), tb>>>();
    scores_tc<<<dim3(Ss / 128, Ss / 256, Bb * Hh), 256, SMEM_BYTES>>>();
    softmax_kernel<<<Bb * Hh * Ss, 256>>>();
    pv_tc<<<dim3(Uu / 128, Ss / 256, Bb * Hh), 256, SMEM_BYTES>>>();
    out_tc<<<dim3(Dd / 128, BS / 256), 256, SMEM_BYTES>>>(out);
}

// round 7
// speedup vs baseline: 1.3200x; 1.3200x over previous
#include <cuda_runtime.h>
#include <cuda_bf16.h>
#include <cstdint>
#include <math.h>

// Problem constants
#define Bb 4
#define Hh 4
#define Ss 2048
#define Dd 512
#define Uu 1024
#define BS 8192          // Bb*Ss
#define HU 4096          // Hh*Uu

// Arch feature gate: tcgen05 only exists on the 'a' variants.
#if defined(__CUDA_ARCH_FEAT_SM103_ALL) || defined(__CUDA_ARCH_FEAT_SM100_ALL)
#define HAS_TCGEN05 1
#else
#define HAS_TCGEN05 0
#endif

// ---------------------------------------------------------------------------
// Device scratch (no cudaMalloc allowed) — round-3 proven fp32 layout
// ---------------------------------------------------------------------------
__device__ float g_xn[BS * Dd];                       // 16 MB
__device__ float g_q[(size_t)Hh * BS * Uu];           // 134 MB
__device__ float g_k[(size_t)Hh * BS * Uu];           // 134 MB
__device__ float g_v[(size_t)Hh * BS * Uu];           // 134 MB
__device__ float g_vt[(size_t)Hh * BS * Uu];          // 134 MB (V^T [h][b][u][t])
__device__ float g_sc[(size_t)Bb * Hh * Ss * Ss];     // 268 MB
__device__ float g_cat[(size_t)BS * HU];              // 134 MB
__device__ float g_wt[(size_t)3 * Hh * Uu * Dd];      // 25 MB  (W^T for q,k,v)
__device__ float g_wot[(size_t)Dd * HU];              // 8 MB   (Wout^T [512][4096])

// ---------------------------------------------------------------------------
// PTX helpers (guarded where sm_103a-only)
// ---------------------------------------------------------------------------
__device__ __forceinline__ uint32_t smem_u32(const void* p) {
    uint32_t a;
    asm("{ .reg .u64 t; cvta.to.shared.u64 t, %1; cvt.u32.u64 %0, t; }" : "=r"(a) : "l"(p));
    return a;
}

#if HAS_TCGEN05
__device__ __forceinline__ uint32_t elect_one() {
    uint32_t pred;
    asm volatile("{\n\t.reg .pred p;\n\telect.sync _|p, 0xFFFFFFFF;\n\t"
                 "selp.b32 %0, 1, 0, p;\n\t}" : "=r"(pred));
    return pred;
}
#define MBAR_INIT(addr, cnt) \
    asm volatile("mbarrier.init.shared.b64 [%0], %1;" :: "r"(addr), "r"(cnt) : "memory")
#define MBAR_WAIT(addr, parity) do {                                              \
    uint32_t _m = (addr), _p = (parity), _d;                                      \
    asm volatile("{\n\t.reg .pred p;\n\t"                                         \
        "mbarrier.try_wait.parity.acquire.cta.shared::cta.b64 p, [%1], %2;\n\t"   \
        "selp.b32 %0, 1, 0, p;\n\t}" : "=r"(_d) : "r"(_m), "r"(_p) : "memory");   \
    if (!_d) {                                                                    \
        asm volatile("{\n\t.reg .pred P1;\n\t"                                    \
            "W_%=:\n\t"                                                           \
            "mbarrier.try_wait.parity.acquire.cta.shared::cta.b64 P1, [%0], %1, 0x989680;\n\t" \
            "@P1 bra.uni D_%=;\n\t"                                               \
            "bra.uni W_%=;\n\t"                                                   \
            "D_%=:\n\t}" :: "r"(_m), "r"(_p) : "memory");                         \
    }                                                                             \
} while (0)
#define TC_ALLOC(smem_addr, n) \
    asm volatile("tcgen05.alloc.cta_group::1.sync.aligned.shared::cta.b32 [%0], %1;" \
                 :: "r"(smem_addr), "r"((uint32_t)(n)) : "memory")
#define TC_DEALLOC(tmem, n) \
    asm volatile("tcgen05.dealloc.cta_group::1.sync.aligned.b32 %0, %1;" :: "r"(tmem), "r"((uint32_t)(n)))
#define TC_COMMIT(mbar) \
    asm volatile("tcgen05.commit.cta_group::1.mbarrier::arrive::one.shared::cluster.b64 [%0];" \
                 :: "r"(mbar) : "memory")
#define TC_FENCE_AFTER()  asm volatile("tcgen05.fence::after_thread_sync;" ::: "memory")
#define TC_WAIT_LD()      asm volatile("tcgen05.wait::ld.sync.aligned;" ::: "memory")
#define FENCE_ASYNC()     asm volatile("fence.proxy.async.shared::cta;" ::: "memory")

#define LDTM_X32(r, addr)                                                         \
    asm volatile("tcgen05.ld.sync.aligned.32x32b.x32.b32 "                        \
        "{%0, %1, %2, %3, %4, %5, %6, %7, %8, %9, %10, %11, %12, %13, %14, %15, " \
        " %16, %17, %18, %19, %20, %21, %22, %23, %24, %25, %26, %27, %28, %29, %30, %31}, [%32];" \
        : "=r"((r)[0]), "=r"((r)[1]), "=r"((r)[2]), "=r"((r)[3]),                 \
          "=r"((r)[4]), "=r"((r)[5]), "=r"((r)[6]), "=r"((r)[7]),                 \
          "=r"((r)[8]), "=r"((r)[9]), "=r"((r)[10]), "=r"((r)[11]),               \
          "=r"((r)[12]), "=r"((r)[13]), "=r"((r)[14]), "=r"((r)[15]),             \
          "=r"((r)[16]), "=r"((r)[17]), "=r"((r)[18]), "=r"((r)[19]),             \
          "=r"((r)[20]), "=r"((r)[21]), "=r"((r)[22]), "=r"((r)[23]),             \
          "=r"((r)[24]), "=r"((r)[25]), "=r"((r)[26]), "=r"((r)[27]),             \
          "=r"((r)[28]), "=r"((r)[29]), "=r"((r)[30]), "=r"((r)[31])              \
        : "r"(addr))

__device__ __forceinline__ void sts64(uint32_t addr, uint32_t a, uint32_t b) {
    asm volatile("st.shared.v2.b32 [%0], {%1,%2};"
                 :: "r"(addr), "r"(a), "r"(b) : "memory");
}

// pack two f32 into bf16x2 (low = x) with a single cvt
__device__ __forceinline__ uint32_t packbf2(float x, float y) {
    uint32_t r;
    asm("cvt.rn.bf16x2.f32 %0, %1, %2;" : "=r"(r) : "f"(y), "f"(x));
    return r;
}

// SMEM descriptor, SW128, LBO=1 (16B), SBO=64 (1024B)
__device__ __forceinline__ uint64_t make_desc(uint32_t addr) {
    const uint64_t base = (2ULL << 61) | (1ULL << 46) | (64ULL << 32) | (1ULL << 16);
    return base | (uint64_t)((addr >> 4) & 0x3FFF);
}
__device__ __forceinline__ void mma_ss(uint32_t d, uint64_t ad, uint64_t bd,
                                       uint32_t idesc, uint32_t en) {
    asm volatile("{\n\t.reg .pred p;\n\tsetp.ne.u32 p, %4, 0;\n\t"
        "tcgen05.mma.cta_group::1.kind::f16 [%0], %1, %2, %3, {%5, %5, %5, %5}, p;\n\t}"
        :: "r"(d), "l"(ad), "l"(bd), "r"(idesc), "r"(en), "r"(0u) : "memory");
}
#endif  // HAS_TCGEN05

// idesc: fp32 accum, bf16 A/B, M=128, N=128 (round-3 proven)
#define IDESC 0x8200490u

// SMEM layout: SINGLE stage (A hi/lo 256x64, B hi/lo 128x64) -> 2 CTAs/SM
#define SM_AHI 0
#define SM_ALO 32768
#define SM_BHI 65536
#define SM_BLO 81920
#define SM_MBAR 98304
#define SM_TPTR 98312
#define SMEM_BYTES 98336

#if HAS_TCGEN05
// ---------------------------------------------------------------------------
// Two-phase stage: fp32 K-major tile (rows x 64) -> hi/lo bf16 SW128 planes.
// Round-3 coalescing (16 thr/row, contiguous LDG.128), batched loads (MLP=8),
// round-6 cvt math. Numerically identical to rounds 3/6.
// NBATCH batches of 8 slots; rows staged = NBATCH * 128.
// ---------------------------------------------------------------------------
template <int NBATCH>
__device__ __forceinline__ void stage(const float* __restrict__ src, int ld,
                                      uint32_t hi, uint32_t lo, int tid) {
#pragma unroll
    for (int b = 0; b < NBATCH; b++) {
        float4 v[8];
#pragma unroll
        for (int i = 0; i < 8; i++) {
            int idx = tid + (b * 8 + i) * 256;
            int r = idx >> 4, q = idx & 15;
            v[i] = *(const float4*)(src + (size_t)r * ld + (q << 2));
        }
#pragma unroll
        for (int i = 0; i < 8; i++) {
            int idx = tid + (b * 8 + i) * 256;
            int r = idx >> 4, q = idx & 15;
            uint32_t h0 = packbf2(v[i].x, v[i].y);
            uint32_t h1 = packbf2(v[i].z, v[i].w);
            uint32_t l0 = packbf2(v[i].x - __uint_as_float(h0 << 16),
                                  v[i].y - __uint_as_float(h0 & 0xFFFF0000u));
            uint32_t l1 = packbf2(v[i].z - __uint_as_float(h1 << 16),
                                  v[i].w - __uint_as_float(h1 & 0xFFFF0000u));
            uint32_t b0 = (uint32_t)(r * 128 + (q << 3));
            uint32_t o = b0 ^ ((b0 >> 3) & 0x70);
            sts64(hi + o, h0, h1);
            sts64(lo + o, l0, l1);
        }
    }
}
#endif

// ---------------------------------------------------------------------------
// Main GEMM: C[256 x 128] = A[256 x kmax] * B[128 x kmax]^T
// fp32 K-major operands, bf16-split 3-pass emulation. kmax multiple of 64.
// Single-stage smem; cross-CTA overlap (2 CTAs/SM) hides staging latency.
// ---------------------------------------------------------------------------
__device__ void gemm_main(const float* __restrict__ A, int lda,
                          const float* __restrict__ B, int ldb,
                          float* __restrict__ C, int ldc, int kmax) {
#if HAS_TCGEN05
    extern __shared__ char smem[];
    uint32_t sb = smem_u32(smem);
    int tid = threadIdx.x;
    int wid = tid >> 5;
    int lane = tid & 31;

    if (wid == 0) TC_ALLOC(sb + SM_TPTR, 256);
    if (tid == 0) MBAR_INIT(sb + SM_MBAR, 1);
    __syncthreads();
    uint32_t tmem = *(volatile uint32_t*)(smem + SM_TPTR);

    int nch = kmax >> 6;

    for (int c = 0; c < nch; c++) {
        if (c > 0) MBAR_WAIT(sb + SM_MBAR, (c - 1) & 1);
        stage<2>(A + c * 64, lda, sb + SM_AHI, sb + SM_ALO, tid);
        stage<1>(B + c * 64, ldb, sb + SM_BHI, sb + SM_BLO, tid);
        FENCE_ASYNC();
        __syncthreads();
        if (wid == 0) {
            if (elect_one()) {
                uint64_t ahi = make_desc(sb + SM_AHI);
                uint64_t alo = make_desc(sb + SM_ALO);
                uint64_t bhi = make_desc(sb + SM_BHI);
                uint64_t blo = make_desc(sb + SM_BLO);
                uint64_t ap[3] = {ahi, ahi, alo};
                uint64_t bp[3] = {bhi, blo, bhi};
#pragma unroll
                for (int half = 0; half < 2; half++) {
                    uint32_t d = tmem + (half << 7);
                    uint64_t ao = (uint64_t)(half * 1024);  // +128 rows * 128B / 16
#pragma unroll
                    for (int pp = 0; pp < 3; pp++) {
#pragma unroll
                        for (int ks = 0; ks < 4; ks++) {
                            uint32_t en = !(c == 0 && pp == 0 && ks == 0);
                            mma_ss(d, ap[pp] + ao + ks * 2, bp[pp] + ks * 2, IDESC, en);
                        }
                    }
                }
                TC_COMMIT(sb + SM_MBAR);
            }
        }
    }

    // Drain final MMA
    if (nch > 0) MBAR_WAIT(sb + SM_MBAR, (nch - 1) & 1);
    TC_FENCE_AFTER();
    __syncthreads();

    // Epilogue: TMEM -> smem bounce -> coalesced gmem (round-3 proven)
    int halfw = wid >> 2;
    int grow = (halfw << 7) + ((wid & 3) << 5) + lane;  // 0..255
    float* sbuf = (float*)smem;                          // reuse stage area
#pragma unroll
    for (int bt = 0; bt < 4; bt++) {
        uint32_t r[32];
        LDTM_X32(r, tmem + (halfw << 7) + bt * 32);
        TC_WAIT_LD();
#pragma unroll
        for (int j = 0; j < 32; j++) sbuf[grow * 33 + j] = __uint_as_float(r[j]);
        __syncthreads();
#pragma unroll
        for (int i = 0; i < 8; i++) {
            int idx = tid + i * 256;
            int row = idx >> 3, c4 = (idx & 7) << 2;
            float4 v = make_float4(sbuf[row * 33 + c4], sbuf[row * 33 + c4 + 1],
                                   sbuf[row * 33 + c4 + 2], sbuf[row * 33 + c4 + 3]);
            *(float4*)(C + (size_t)row * ldc + bt * 32 + c4) = v;
        }
        __syncthreads();
    }
    if (wid == 0) TC_DEALLOC(tmem, 256);

#else  // ----- fp32 SIMT fallback (plain sm_103 PTX pass) -----
    extern __shared__ char smem[];
    float (*As)[128] = (float (*)[128])smem;                    // [16][128]
    float (*Bs)[128] = (float (*)[128])(smem + 16 * 128 * 4);   // [16][128]
    const int tid = threadIdx.x;
    const int tx = tid & 15, ty = tid >> 4;

    for (int half = 0; half < 2; half++) {
        const float* Ah = A + (size_t)(half * 128) * lda;
        float acc[8][8];
#pragma unroll
        for (int i = 0; i < 8; i++)
#pragma unroll
            for (int j = 0; j < 8; j++) acc[i][j] = 0.0f;

        for (int k0 = 0; k0 < kmax; k0 += 16) {
#pragma unroll
            for (int i = 0; i < 2; i++) {
                int idx = tid + i * 256;
                int r = idx >> 2, c = (idx & 3) << 2;
                float4 v = *(const float4*)(Ah + (size_t)r * lda + k0 + c);
                As[c + 0][r] = v.x; As[c + 1][r] = v.y;
                As[c + 2][r] = v.z; As[c + 3][r] = v.w;
                float4 w = *(const float4*)(B + (size_t)r * ldb + k0 + c);
                Bs[c + 0][r] = w.x; Bs[c + 1][r] = w.y;
                Bs[c + 2][r] = w.z; Bs[c + 3][r] = w.w;
            }
            __syncthreads();
#pragma unroll
            for (int k = 0; k < 16; k++) {
                float a[8], b[8];
#pragma unroll
                for (int j = 0; j < 8; j++) { a[j] = As[k][ty * 8 + j]; b[j] = Bs[k][tx * 8 + j]; }
#pragma unroll
                for (int i = 0; i < 8; i++)
#pragma unroll
                    for (int j = 0; j < 8; j++)
                        acc[i][j] = fmaf(a[i], b[j], acc[i][j]);
            }
            __syncthreads();
        }
#pragma unroll
        for (int i = 0; i < 8; i++) {
            float* cr = C + (size_t)(half * 128 + ty * 8 + i) * ldc + tx * 8;
#pragma unroll
            for (int j = 0; j < 8; j++) cr[j] = acc[i][j];
        }
        __syncthreads();
    }
#endif
}

// ---------------------------------------------------------------------------
// Block reduction (256 threads)
// ---------------------------------------------------------------------------
__device__ __forceinline__ float block_reduce(float v, bool is_max) {
    __shared__ float red[8];
    int lane = threadIdx.x & 31, w = threadIdx.x >> 5;
#pragma unroll
    for (int o = 16; o; o >>= 1) {
        float u = __shfl_xor_sync(0xffffffffu, v, o);
        v = is_max ? fmaxf(v, u) : (v + u);
    }
    if (lane == 0) red[w] = v;
    __syncthreads();
    if (w == 0) {
        float t = (lane < 8) ? red[lane] : (is_max ? -3.4e38f : 0.0f);
#pragma unroll
        for (int o = 4; o; o >>= 1) {
            float u = __shfl_xor_sync(0xffffffffu, t, o);
            t = is_max ? fmaxf(t, u) : (t + u);
        }
        if (lane == 0) red[0] = t;
    }
    __syncthreads();
    float r = red[0];
    __syncthreads();
    return r;
}

// ---------------------------------------------------------------------------
// LayerNorm
// ---------------------------------------------------------------------------
__global__ void ln_kernel(const float* __restrict__ x,
                          const float* __restrict__ gamma,
                          const float* __restrict__ beta) {
    int row = blockIdx.x;
    const float* xr = x + (size_t)row * Dd;
    float* o = g_xn + (size_t)row * Dd;
    int t = threadIdx.x;
    float v0 = xr[t], v1 = xr[t + 256];
    float mu = block_reduce(v0 + v1, false) * (1.0f / Dd);
    float d0 = v0 - mu, d1 = v1 - mu;
    float var = block_reduce(d0 * d0 + d1 * d1, false) * (1.0f / Dd);
    float inv = 1.0f / sqrtf(var + 1e-6f);
    o[t]       = d0 * inv * gamma[t]       + beta[t];
    o[t + 256] = d1 * inv * gamma[t + 256] + beta[t + 256];
}

// ---------------------------------------------------------------------------
// Tiled fp32 transpose: [R][C] -> [C][R], batched over blockIdx.z
// ---------------------------------------------------------------------------
__device__ __forceinline__ void tr_dev(const float* __restrict__ src,
                                       float* __restrict__ dst, int R, int C) {
    __shared__ float t[32][33];
    size_t bo = (size_t)blockIdx.z * R * C;
    int c0 = blockIdx.x * 32, r0 = blockIdx.y * 32;
    int tx = threadIdx.x, ty = threadIdx.y;
#pragma unroll
    for (int i = 0; i < 4; i++)
        t[ty + i * 8][tx] = src[bo + (size_t)(r0 + ty + i * 8) * C + c0 + tx];
    __syncthreads();
#pragma unroll
    for (int i = 0; i < 4; i++)
        dst[bo + (size_t)(c0 + ty + i * 8) * R + r0 + tx] = t[tx][ty + i * 8];
}

__global__ void trw_kernel(const float* __restrict__ src, int wsel) {
    tr_dev(src, g_wt + (size_t)wsel * Hh * Uu * Dd, Dd, Uu);
}
__global__ void trwo_kernel(const float* __restrict__ src) {
    tr_dev(src, g_wot, HU, Dd);
}
__global__ void trv_kernel() {
    tr_dev(g_v, g_vt, Ss, Uu);
}

// ---------------------------------------------------------------------------
// GEMM wrappers
// ---------------------------------------------------------------------------
__global__ __launch_bounds__(256, 2) void qkv_tc() {
    int z = blockIdx.z;
    int which = z >> 2, h = z & 3;
    const float* Bp = g_wt + (size_t)z * Uu * Dd;
    float* Cb = (which == 0 ? g_q : which == 1 ? g_k : g_v) + (size_t)h * BS * Uu;
    int br = blockIdx.y * 256, bc = blockIdx.x * 128;
    gemm_main(g_xn + (size_t)br * Dd, Dd, Bp + (size_t)bc * Dd, Dd,
              Cb + (size_t)br * Uu + bc, Uu, Dd);
}

__global__ __launch_bounds__(256, 2) void scores_tc() {
    int br = blockIdx.y * 256, bc = blockIdx.x * 128;
    if (bc >= br + 256) return;  // fully above causal diagonal
    int z = blockIdx.z, b = z >> 2, h = z & 3;
    const float* Qh = g_q + ((size_t)h * BS + (size_t)b * Ss) * Uu;
    const float* Kh = g_k + ((size_t)h * BS + (size_t)b * Ss) * Uu;
    float* C = g_sc + (size_t)(b * Hh + h) * Ss * Ss;
    gemm_main(Qh + (size_t)br * Uu, Uu, Kh + (size_t)bc * Uu, Uu,
              C + (size_t)br * Ss + bc, Ss, Uu);
}

__global__ __launch_bounds__(256, 2) void pv_tc() {
    int z = blockIdx.z, b = z >> 2, h = z & 3;
    int br = blockIdx.y * 256, bc = blockIdx.x * 128;
    const float* P = g_sc + (size_t)(b * Hh + h) * Ss * Ss;
    const float* Vt = g_vt + (size_t)(h * Bb + b) * Uu * Ss;
    float* C = g_cat + (size_t)(b * Ss + br) * HU + h * Uu + bc;
    gemm_main(P + (size_t)br * Ss, Ss, Vt + (size_t)bc * Ss, Ss, C, HU, br + 256);
}

__global__ __launch_bounds__(256, 2) void out_tc(float* __restrict__ out) {
    int br = blockIdx.y * 256, bc = blockIdx.x * 128;
    gemm_main(g_cat + (size_t)br * HU, HU, g_wot + (size_t)bc * HU, HU,
              out + (size_t)br * Dd + bc, Dd, HU);
}

// ---------------------------------------------------------------------------
// Softmax (causal, unscaled). Zero-fills (i, 256-block end) for PV.
// ---------------------------------------------------------------------------
__global__ void softmax_kernel() {
    int row = blockIdx.x;
    int i = row & (Ss - 1);
    float* r = g_sc + (size_t)row * Ss;
    int n = i + 1;
    int t = threadIdx.x;

    float v[8];
    float m = -3.4e38f;
#pragma unroll
    for (int c = 0; c < 8; c++) {
        int j = t + c * 256;
        v[c] = (j < n) ? r[j] : -3.4e38f;
        m = fmaxf(m, v[c]);
    }
    m = block_reduce(m, true);
    float s = 0.0f;
#pragma unroll
    for (int c = 0; c < 8; c++) {
        v[c] = expf(v[c] - m);
        s += v[c];
    }
    s = block_reduce(s, false);
    float inv = 1.0f / s;
#pragma unroll
    for (int c = 0; c < 8; c++) {
        int j = t + c * 256;
        if (j < n) r[j] = v[c] * inv;
    }
    int end = ((i >> 8) + 1) << 8;   // 256-aligned (PV tile k-extent)
    for (int j = n + t; j < end; j += 256) r[j] = 0.0f;
}

// ---------------------------------------------------------------------------
extern "C" void kernel_launch(void* const* d_in, const int* in_sizes, int n_in,
                              void* d_out, int out_size) {
    const float* x     = (const float*)d_in[0];
    const float* gamma = (const float*)d_in[1];
    const float* beta  = (const float*)d_in[2];
    const float* Wq    = (const float*)d_in[3];
    const float* Wk    = (const float*)d_in[4];
    const float* Wv    = (const float*)d_in[5];
    const float* Wout  = (const float*)d_in[6];
    float* out = (float*)d_out;

    cudaFuncSetAttribute(qkv_tc,    cudaFuncAttributeMaxDynamicSharedMemorySize, SMEM_BYTES);
    cudaFuncSetAttribute(scores_tc, cudaFuncAttributeMaxDynamicSharedMemorySize, SMEM_BYTES);
    cudaFuncSetAttribute(pv_tc,     cudaFuncAttributeMaxDynamicSharedMemorySize, SMEM_BYTES);
    cudaFuncSetAttribute(out_tc,    cudaFuncAttributeMaxDynamicSharedMemorySize, SMEM_BYTES);

    dim3 tb(32, 8);

    ln_kernel<<<BS, 256>>>(x, gamma, beta);
    trw_kernel<<<dim3(Uu / 32, Dd / 32, Hh), tb>>>(Wq, 0);
    trw_kernel<<<dim3(Uu / 32, Dd / 32, Hh), tb>>>(Wk, 1);
    trw_kernel<<<dim3(Uu / 32, Dd / 32, Hh), tb>>>(Wv, 2);
    trwo_kernel<<<dim3(Dd / 32, HU / 32, 1), tb>>>(Wout);

    qkv_tc<<<dim3(Uu / 128, BS / 256, 12), 256, SMEM_BYTES>>>();
    trv_kernel<<<dim3(Uu / 32, Ss / 32, Bb * Hh), tb>>>();
    scores_tc<<<dim3(Ss / 128, Ss / 256, Bb * Hh), 256, SMEM_BYTES>>>();
    softmax_kernel<<<Bb * Hh * Ss, 256>>>();
    pv_tc<<<dim3(Uu / 128, Ss / 256, Bb * Hh), 256, SMEM_BYTES>>>();
    out_tc<<<dim3(Dd / 128, BS / 256), 256, SMEM_BYTES>>>(out);
}